// round 1
// baseline (speedup 1.0000x reference)
#include <cuda_runtime.h>

#define NN 50000
#define NE 1600000
#define ET (NE + NN)
#define NG 64

// ---------------- scratch (static device globals; no allocation) ----------------
__device__ float g_xl1[NN * 64];
__device__ float g_as1[NN * 2];
__device__ float g_ad1[NN * 2];
__device__ float g_h1[NN * 64];
__device__ float g_xl2[NN * 128];
__device__ float g_as2[NN];
__device__ float g_ad2[NN];
__device__ int   g_deg[NN];
__device__ int   g_off[NN + 1];
__device__ int   g_cur[NN];
__device__ int   g_srcs[ET];
__device__ float g_pool[NG * 128];
__device__ int   g_cnt[NG];
__device__ int   g_is64;

// ---------------- dtype detection (int64 vs int32 edge/batch buffers) -----------
__global__ void k_detect(const int* __restrict__ ei32) {
    if (threadIdx.x == 0 && blockIdx.x == 0) {
        int ok = 1;
        for (int i = 0; i < 64; i++) {
            if (ei32[2 * i + 1] != 0) ok = 0;   // high words of int64 LE must be 0
        }
        g_is64 = ok;
    }
}

__device__ __forceinline__ int idx_at(const void* p, int i) {
    if (g_is64) return (int)((const long long*)p)[i];
    return ((const int*)p)[i];
}

// ---------------- zero accumulators ----------------
__global__ void k_zero() {
    int i = blockIdx.x * 256 + threadIdx.x;
    if (i < NN) g_deg[i] = 0;
    if (i < NG * 128) g_pool[i] = 0.f;
    if (i < NG) g_cnt[i] = 0;
}

// ---------------- CSR build ----------------
__global__ void k_hist(const void* __restrict__ ei) {
    int e = blockIdx.x * 256 + threadIdx.x;
    if (e < NE) {
        int dst = idx_at(ei, NE + e);
        atomicAdd(&g_deg[dst], 1);
    }
}

__global__ void k_scan() {
    __shared__ int warp_sums[32];
    __shared__ int s_carry;
    int tid = threadIdx.x, lane = tid & 31, wid = tid >> 5;
    if (tid == 0) s_carry = 0;
    __syncthreads();
    for (int base = 0; base < NN; base += 1024) {
        int i = base + tid;
        int v = (i < NN) ? (g_deg[i] + 1) : 0;   // +1 for the self loop
        int x = v;
        #pragma unroll
        for (int o = 1; o < 32; o <<= 1) {
            int t = __shfl_up_sync(0xffffffffu, x, o);
            if (lane >= o) x += t;
        }
        if (lane == 31) warp_sums[wid] = x;
        __syncthreads();
        if (wid == 0) {
            int w = warp_sums[lane];
            int y = w;
            #pragma unroll
            for (int o = 1; o < 32; o <<= 1) {
                int t = __shfl_up_sync(0xffffffffu, y, o);
                if (lane >= o) y += t;
            }
            warp_sums[lane] = y - w;  // exclusive warp offsets
        }
        __syncthreads();
        int incl = x + warp_sums[wid];
        int excl = incl - v;
        if (i < NN) {
            g_off[i] = s_carry + excl;
            g_cur[i] = s_carry + excl;
        }
        __syncthreads();
        if (tid == 1023) s_carry += incl;  // padded lanes contribute 0
        __syncthreads();
    }
    if (tid == 0) g_off[NN] = s_carry;
}

__global__ void k_fill(const void* __restrict__ ei) {
    int i = blockIdx.x * 256 + threadIdx.x;
    if (i >= ET) return;
    int src, dst;
    if (i < NE) {
        src = idx_at(ei, i);
        dst = idx_at(ei, NE + i);
    } else {
        src = i - NE;   // self loop
        dst = src;
    }
    int p = atomicAdd(&g_cur[dst], 1);
    g_srcs[p] = src;
}

// ---------------- layer 1: xl1 = x @ W1 ; a_src/a_dst scores ----------------
// block = 128 threads = 8 nodes x 16 threads; each thread computes 4 of 64 cols.
__global__ void k_gemm1(const float* __restrict__ x, const float* __restrict__ W1,
                        const float* __restrict__ as, const float* __restrict__ ad) {
    __shared__ float xsh[8 * 128];
    int tid = threadIdx.x;
    int base = blockIdx.x * 8;
    for (int i = tid; i < 1024; i += 128) xsh[i] = x[base * 128 + i];
    __syncthreads();
    int nl = tid >> 4, t4 = tid & 15;
    const float4* W4 = (const float4*)W1;
    float4 acc = make_float4(0.f, 0.f, 0.f, 0.f);
    const float* xr = &xsh[nl * 128];
    #pragma unroll 8
    for (int k = 0; k < 128; k++) {
        float xv = xr[k];
        float4 w = W4[k * 16 + t4];
        acc.x += xv * w.x; acc.y += xv * w.y; acc.z += xv * w.z; acc.w += xv * w.w;
    }
    int n = base + nl;
    ((float4*)g_xl1)[n * 16 + t4] = acc;
    int h = t4 >> 3;
    const float4* as4 = (const float4*)as;
    const float4* ad4 = (const float4*)ad;
    float4 a = as4[h * 8 + (t4 & 7)];
    float4 d = ad4[h * 8 + (t4 & 7)];
    float ps = acc.x * a.x + acc.y * a.y + acc.z * a.z + acc.w * a.w;
    float pd = acc.x * d.x + acc.y * d.y + acc.z * d.z + acc.w * d.w;
    #pragma unroll
    for (int o = 1; o < 8; o <<= 1) {
        ps += __shfl_xor_sync(0xffffffffu, ps, o);
        pd += __shfl_xor_sync(0xffffffffu, pd, o);
    }
    if ((t4 & 7) == 0) {
        g_as1[n * 2 + h] = ps;
        g_ad1[n * 2 + h] = pd;
    }
}

// ---------------- layer 1 aggregation: online softmax per dst node ----------------
// one warp per node; lane owns (h0,d=lane) and (h1,d=lane)
__global__ void k_agg1(const float* __restrict__ b1) {
    int n = blockIdx.x * 8 + (threadIdx.x >> 5);
    int lane = threadIdx.x & 31;
    float2 adv = ((const float2*)g_ad1)[n];
    float m0 = -1e30f, m1 = -1e30f, s0 = 0.f, s1 = 0.f, a0 = 0.f, a1 = 0.f;
    int beg = g_off[n], end = g_off[n + 1];
    for (int j = beg; j < end; j++) {
        int src = g_srcs[j];
        float2 asv = ((const float2*)g_as1)[src];
        float e0 = asv.x + adv.x; e0 = e0 > 0.f ? e0 : 0.2f * e0;
        float e1 = asv.y + adv.y; e1 = e1 > 0.f ? e1 : 0.2f * e1;
        float x0 = g_xl1[src * 64 + lane];
        float x1 = g_xl1[src * 64 + 32 + lane];
        float nm0 = fmaxf(m0, e0), nm1 = fmaxf(m1, e1);
        float c0 = __expf(m0 - nm0), c1 = __expf(m1 - nm1);
        float p0 = __expf(e0 - nm0), p1 = __expf(e1 - nm1);
        s0 = s0 * c0 + p0;        s1 = s1 * c1 + p1;
        a0 = a0 * c0 + p0 * x0;   a1 = a1 * c1 + p1 * x1;
        m0 = nm0; m1 = nm1;
    }
    float o0 = a0 / s0 + b1[lane];
    float o1 = a1 / s1 + b1[32 + lane];
    o0 = o0 > 0.f ? o0 : (__expf(o0) - 1.f);   // ELU
    o1 = o1 > 0.f ? o1 : (__expf(o1) - 1.f);
    g_h1[n * 64 + lane] = o0;
    g_h1[n * 64 + 32 + lane] = o1;
}

// ---------------- layer 2: xl2 = h1 @ W2 ; scores ----------------
// block = 128 threads = 4 nodes x 32 threads; each thread computes 4 of 128 cols.
__global__ void k_gemm2(const float* __restrict__ W2, const float* __restrict__ as,
                        const float* __restrict__ ad) {
    __shared__ float hsh[4 * 64];
    int tid = threadIdx.x;
    int base = blockIdx.x * 4;
    for (int i = tid; i < 256; i += 128) hsh[i] = g_h1[base * 64 + i];
    __syncthreads();
    int nl = tid >> 5, t = tid & 31;
    const float4* W4 = (const float4*)W2;
    float4 acc = make_float4(0.f, 0.f, 0.f, 0.f);
    const float* hr = &hsh[nl * 64];
    #pragma unroll 8
    for (int k = 0; k < 64; k++) {
        float hv = hr[k];
        float4 w = W4[k * 32 + t];
        acc.x += hv * w.x; acc.y += hv * w.y; acc.z += hv * w.z; acc.w += hv * w.w;
    }
    int n = base + nl;
    ((float4*)g_xl2)[n * 32 + t] = acc;
    float4 a = ((const float4*)as)[t];
    float4 d = ((const float4*)ad)[t];
    float ps = acc.x * a.x + acc.y * a.y + acc.z * a.z + acc.w * a.w;
    float pd = acc.x * d.x + acc.y * d.y + acc.z * d.z + acc.w * d.w;
    #pragma unroll
    for (int o = 1; o < 32; o <<= 1) {
        ps += __shfl_xor_sync(0xffffffffu, ps, o);
        pd += __shfl_xor_sync(0xffffffffu, pd, o);
    }
    if (t == 0) { g_as2[n] = ps; g_ad2[n] = pd; }
}

// ---------------- layer 2 aggregation + ELU + pooled accumulation ----------------
__global__ void k_agg2(const float* __restrict__ b2, const void* __restrict__ batch) {
    int n = blockIdx.x * 8 + (threadIdx.x >> 5);
    int lane = threadIdx.x & 31;
    float adv = g_ad2[n];
    float m = -1e30f, s = 0.f;
    float4 acc = make_float4(0.f, 0.f, 0.f, 0.f);
    int beg = g_off[n], end = g_off[n + 1];
    const float4* X = (const float4*)g_xl2;
    for (int j = beg; j < end; j++) {
        int src = g_srcs[j];
        float e = g_as2[src] + adv; e = e > 0.f ? e : 0.2f * e;
        float4 xv = X[src * 32 + lane];
        float nm = fmaxf(m, e);
        float c = __expf(m - nm), p = __expf(e - nm);
        s = s * c + p;
        acc.x = acc.x * c + p * xv.x;
        acc.y = acc.y * c + p * xv.y;
        acc.z = acc.z * c + p * xv.z;
        acc.w = acc.w * c + p * xv.w;
        m = nm;
    }
    float inv = 1.f / s;
    float4 bb = ((const float4*)b2)[lane];
    float v0 = acc.x * inv + bb.x; v0 = v0 > 0.f ? v0 : (__expf(v0) - 1.f);
    float v1 = acc.y * inv + bb.y; v1 = v1 > 0.f ? v1 : (__expf(v1) - 1.f);
    float v2 = acc.z * inv + bb.z; v2 = v2 > 0.f ? v2 : (__expf(v2) - 1.f);
    float v3 = acc.w * inv + bb.w; v3 = v3 > 0.f ? v3 : (__expf(v3) - 1.f);
    int b = idx_at(batch, n);
    float* pp = &g_pool[b * 128 + lane * 4];
    atomicAdd(pp + 0, v0);
    atomicAdd(pp + 1, v1);
    atomicAdd(pp + 2, v2);
    atomicAdd(pp + 3, v3);
    if (lane == 0) atomicAdd(&g_cnt[b], 1);
}

// ---------------- final: mean pool -> out ----------------
__global__ void k_final(float* __restrict__ out) {
    int i = blockIdx.x * 256 + threadIdx.x;
    if (i < NG * 128) {
        int g = i >> 7;
        float c = (float)g_cnt[g];
        out[i] = g_pool[i] / fmaxf(c, 1.f);
    }
}

extern "C" void kernel_launch(void* const* d_in, const int* in_sizes, int n_in,
                              void* d_out, int out_size) {
    const float* x   = (const float*)d_in[0];
    const void*  ei  = d_in[1];               // int64 or int32, detected on device
    const void*  bat = d_in[2];
    const float* W1  = (const float*)d_in[3];
    const float* as1 = (const float*)d_in[4];
    const float* ad1 = (const float*)d_in[5];
    const float* b1  = (const float*)d_in[6];
    const float* W2  = (const float*)d_in[7];
    const float* as2 = (const float*)d_in[8];
    const float* ad2 = (const float*)d_in[9];
    const float* b2  = (const float*)d_in[10];
    float* out = (float*)d_out;

    k_detect<<<1, 32>>>((const int*)ei);
    k_zero<<<(NN + 255) / 256, 256>>>();
    k_hist<<<(NE + 255) / 256, 256>>>(ei);
    k_scan<<<1, 1024>>>();
    k_fill<<<(ET + 255) / 256, 256>>>(ei);
    k_gemm1<<<NN / 8, 128>>>(x, W1, as1, ad1);
    k_agg1<<<NN / 8, 256>>>(b1);
    k_gemm2<<<NN / 4, 128>>>(W2, as2, ad2);
    k_agg2<<<NN / 8, 256>>>(b2, bat);
    k_final<<<(NG * 128 + 255) / 256, 256>>>(out);
}

// round 3
// speedup vs baseline: 1.3371x; 1.3371x over previous
#include <cuda_runtime.h>

#define NN 50000
#define NE 1600000
#define ET (NE + NN)
#define NG 64
#define NSB ((NN + 255) / 256)   // 196 scan blocks

// ---------------- scratch (static device globals; no allocation) ----------------
__device__ float g_xl1[NN * 64];
__device__ float g_as1[NN * 2];
__device__ float g_ad1[NN * 2];
__device__ float g_h1[NN * 64];
__device__ float g_xl2[NN * 128];
__device__ float g_as2[NN];
__device__ float g_ad2[NN];
__device__ int   g_deg[NN];
__device__ int   g_off[NN + 1];
__device__ int   g_cur[NN];
__device__ int   g_srcs[ET];
__device__ int   g_bsum[NSB];
__device__ int   g_boff[NSB];
__device__ float g_pool[NG * 128];
__device__ int   g_cnt[NG];
__device__ int   g_is64;

// ---------------- f32x2 packed helpers ----------------
__device__ __forceinline__ unsigned long long pk2(float x, float y) {
    unsigned long long r;
    asm("mov.b64 %0,{%1,%2};" : "=l"(r) : "f"(x), "f"(y));
    return r;
}
__device__ __forceinline__ float2 upk2(unsigned long long v) {
    float x, y;
    asm("mov.b64 {%0,%1},%2;" : "=f"(x), "=f"(y) : "l"(v));
    return make_float2(x, y);
}
__device__ __forceinline__ unsigned long long ffma2(unsigned long long a,
                                                    unsigned long long b,
                                                    unsigned long long c) {
    unsigned long long d;
    asm("fma.rn.f32x2 %0,%1,%2,%3;" : "=l"(d) : "l"(a), "l"(b), "l"(c));
    return d;
}

__device__ __forceinline__ int idx_at(const void* p, int i) {
    if (g_is64) return (int)((const long long*)p)[i];
    return ((const int*)p)[i];
}

// ---------------- zero + dtype detect ----------------
__global__ void k_zero(const int* __restrict__ ei32) {
    int i = blockIdx.x * 256 + threadIdx.x;
    if (i < NN) g_deg[i] = 0;
    if (i < NG * 128) g_pool[i] = 0.f;
    if (i < NG) g_cnt[i] = 0;
    if (i == 0) {
        int ok = 1;
        for (int k = 0; k < 64; k++)
            if (ei32[2 * k + 1] != 0) ok = 0;
        g_is64 = ok;
    }
}

// ---------------- CSR build ----------------
__global__ void k_hist(const void* __restrict__ ei) {
    int e = blockIdx.x * 256 + threadIdx.x;
    if (e < NE) atomicAdd(&g_deg[idx_at(ei, NE + e)], 1);
}

__global__ void k_scan1() {
    int t = threadIdx.x, i = blockIdx.x * 256 + t;
    int v = (i < NN) ? (g_deg[i] + 1) : 0;
    #pragma unroll
    for (int o = 16; o > 0; o >>= 1) v += __shfl_xor_sync(0xffffffffu, v, o);
    __shared__ int ws[8];
    if ((t & 31) == 0) ws[t >> 5] = v;
    __syncthreads();
    if (t == 0) {
        int s = 0;
        #pragma unroll
        for (int w = 0; w < 8; w++) s += ws[w];
        g_bsum[blockIdx.x] = s;
    }
}

__global__ void k_scan2() {
    __shared__ int sh[256];
    int t = threadIdx.x;
    int v = (t < NSB) ? g_bsum[t] : 0;
    sh[t] = v;
    __syncthreads();
    for (int o = 1; o < 256; o <<= 1) {
        int u = (t >= o) ? sh[t - o] : 0;
        __syncthreads();
        sh[t] += u;
        __syncthreads();
    }
    if (t < NSB) g_boff[t] = sh[t] - v;
    if (t == NSB - 1) g_off[NN] = sh[t];
}

__global__ void k_scan3() {
    int t = threadIdx.x, lane = t & 31, wid = t >> 5;
    int i = blockIdx.x * 256 + t;
    int v = (i < NN) ? (g_deg[i] + 1) : 0;
    int x = v;
    #pragma unroll
    for (int o = 1; o < 32; o <<= 1) {
        int u = __shfl_up_sync(0xffffffffu, x, o);
        if (lane >= o) x += u;
    }
    __shared__ int ws[8];
    if (lane == 31) ws[wid] = x;
    __syncthreads();
    if (wid == 0 && lane < 8) {
        int w = ws[lane];
        int y = w;
        #pragma unroll
        for (int o = 1; o < 8; o <<= 1) {
            int u = __shfl_up_sync(0xffu, y, o);
            if (lane >= o) y += u;
        }
        ws[lane] = y - w;
    }
    __syncthreads();
    int excl = x - v + ws[wid] + g_boff[blockIdx.x];
    if (i < NN) { g_off[i] = excl; g_cur[i] = excl; }
}

__global__ void k_fill(const void* __restrict__ ei) {
    int i = blockIdx.x * 256 + threadIdx.x;
    if (i >= ET) return;
    int src, dst;
    if (i < NE) { src = idx_at(ei, i); dst = idx_at(ei, NE + i); }
    else        { src = i - NE; dst = src; }
    int p = atomicAdd(&g_cur[dst], 1);
    g_srcs[p] = src;
}

// ---------------- layer 1 GEMM: xl1 = x @ W1 (+ attention scores) ----------------
// 128 threads = 8 node-slots x 16 col-groups; each thread: 2 nodes x 4 cols, f32x2.
__global__ void k_gemm1(const float* __restrict__ x, const float* __restrict__ W1,
                        const float* __restrict__ as, const float* __restrict__ ad) {
    __shared__ float xsh[16 * 128];
    int tid = threadIdx.x;
    int base = blockIdx.x * 16;
    {
        float4* d4 = (float4*)xsh;
        const float4* s4 = (const float4*)(x + (long)base * 128);
        for (int i = tid; i < 512; i += 128) d4[i] = s4[i];
    }
    __syncthreads();
    int nl = tid >> 4, t4 = tid & 15;
    const float4* W4 = (const float4*)W1;
    unsigned long long aA0 = 0, aA1 = 0, aB0 = 0, aB1 = 0;
    const float* xa = &xsh[nl * 128];
    const float* xb = &xsh[(nl + 8) * 128];
    #pragma unroll 4
    for (int k = 0; k < 128; k++) {
        float4 w = W4[k * 16 + t4];
        unsigned long long w01 = pk2(w.x, w.y), w23 = pk2(w.z, w.w);
        unsigned long long va = pk2(xa[k], xa[k]);
        unsigned long long vb = pk2(xb[k], xb[k]);
        aA0 = ffma2(va, w01, aA0); aA1 = ffma2(va, w23, aA1);
        aB0 = ffma2(vb, w01, aB0); aB1 = ffma2(vb, w23, aB1);
    }
    float2 A0 = upk2(aA0), A1 = upk2(aA1), B0 = upk2(aB0), B1 = upk2(aB1);
    int nA = base + nl, nB = base + nl + 8;
    ((float4*)g_xl1)[nA * 16 + t4] = make_float4(A0.x, A0.y, A1.x, A1.y);
    ((float4*)g_xl1)[nB * 16 + t4] = make_float4(B0.x, B0.y, B1.x, B1.y);
    float4 a = ((const float4*)as)[t4];
    float4 d = ((const float4*)ad)[t4];
    float psA = A0.x * a.x + A0.y * a.y + A1.x * a.z + A1.y * a.w;
    float pdA = A0.x * d.x + A0.y * d.y + A1.x * d.z + A1.y * d.w;
    float psB = B0.x * a.x + B0.y * a.y + B1.x * a.z + B1.y * a.w;
    float pdB = B0.x * d.x + B0.y * d.y + B1.x * d.z + B1.y * d.w;
    #pragma unroll
    for (int o = 1; o < 8; o <<= 1) {
        psA += __shfl_xor_sync(0xffffffffu, psA, o);
        pdA += __shfl_xor_sync(0xffffffffu, pdA, o);
        psB += __shfl_xor_sync(0xffffffffu, psB, o);
        pdB += __shfl_xor_sync(0xffffffffu, pdB, o);
    }
    if ((t4 & 7) == 0) {
        int h = t4 >> 3;
        g_as1[nA * 2 + h] = psA;  g_ad1[nA * 2 + h] = pdA;
        g_as1[nB * 2 + h] = psB;  g_ad1[nB * 2 + h] = pdB;
    }
}

// ---------------- layer 1 aggregation (plain-exp softmax, 2-edge unroll) --------
__global__ void k_agg1(const float* __restrict__ b1) {
    int n = blockIdx.x * 8 + (threadIdx.x >> 5);
    int lane = threadIdx.x & 31;
    float2 adv = ((const float2*)g_ad1)[n];
    unsigned long long s01 = 0, acc0 = 0, acc1 = 0;
    const unsigned long long one2 = 0x3f8000003f800000ull;  // {1.f,1.f}
    int beg = g_off[n], end = g_off[n + 1];
    int j = beg;
    for (; j + 1 < end; j += 2) {
        int sa = g_srcs[j], sb = g_srcs[j + 1];
        float2 ea = ((const float2*)g_as1)[sa];
        float2 eb = ((const float2*)g_as1)[sb];
        float xa0 = g_xl1[sa * 64 + lane],      xa1 = g_xl1[sa * 64 + 32 + lane];
        float xb0 = g_xl1[sb * 64 + lane],      xb1 = g_xl1[sb * 64 + 32 + lane];
        float e0 = ea.x + adv.x; e0 = e0 > 0.f ? e0 : 0.2f * e0;
        float e1 = ea.y + adv.y; e1 = e1 > 0.f ? e1 : 0.2f * e1;
        float f0 = eb.x + adv.x; f0 = f0 > 0.f ? f0 : 0.2f * f0;
        float f1 = eb.y + adv.y; f1 = f1 > 0.f ? f1 : 0.2f * f1;
        unsigned long long pa = pk2(__expf(e0), __expf(e1));
        unsigned long long pb = pk2(__expf(f0), __expf(f1));
        s01  = ffma2(pa, one2, s01);
        s01  = ffma2(pb, one2, s01);
        acc0 = ffma2(pa, pk2(xa0, xa1), acc0);
        acc1 = ffma2(pb, pk2(xb0, xb1), acc1);
    }
    if (j < end) {
        int sa = g_srcs[j];
        float2 ea = ((const float2*)g_as1)[sa];
        float xa0 = g_xl1[sa * 64 + lane], xa1 = g_xl1[sa * 64 + 32 + lane];
        float e0 = ea.x + adv.x; e0 = e0 > 0.f ? e0 : 0.2f * e0;
        float e1 = ea.y + adv.y; e1 = e1 > 0.f ? e1 : 0.2f * e1;
        unsigned long long pa = pk2(__expf(e0), __expf(e1));
        s01  = ffma2(pa, one2, s01);
        acc0 = ffma2(pa, pk2(xa0, xa1), acc0);
    }
    float2 s = upk2(s01);
    float2 u = upk2(acc0), v = upk2(acc1);
    float o0 = (u.x + v.x) / s.x + b1[lane];
    float o1 = (u.y + v.y) / s.y + b1[32 + lane];
    o0 = o0 > 0.f ? o0 : (__expf(o0) - 1.f);
    o1 = o1 > 0.f ? o1 : (__expf(o1) - 1.f);
    g_h1[n * 64 + lane] = o0;
    g_h1[n * 64 + 32 + lane] = o1;
}

// ---------------- layer 2 GEMM: xl2 = h1 @ W2 (+ scores) ----------------
// 128 threads = 4 node-slots x 32 col-groups; each thread: 2 nodes x 4 cols.
__global__ void k_gemm2(const float* __restrict__ W2, const float* __restrict__ as,
                        const float* __restrict__ ad) {
    __shared__ float hsh[8 * 64];
    int tid = threadIdx.x;
    int base = blockIdx.x * 8;
    {
        float4* d4 = (float4*)hsh;
        const float4* s4 = (const float4*)(g_h1 + (long)base * 64);
        if (tid < 128) d4[tid] = s4[tid];
    }
    __syncthreads();
    int nl = tid >> 5, t = tid & 31;
    const float4* W4 = (const float4*)W2;
    unsigned long long aA0 = 0, aA1 = 0, aB0 = 0, aB1 = 0;
    const float* xa = &hsh[nl * 64];
    const float* xb = &hsh[(nl + 4) * 64];
    #pragma unroll 4
    for (int k = 0; k < 64; k++) {
        float4 w = W4[k * 32 + t];
        unsigned long long w01 = pk2(w.x, w.y), w23 = pk2(w.z, w.w);
        unsigned long long va = pk2(xa[k], xa[k]);
        unsigned long long vb = pk2(xb[k], xb[k]);
        aA0 = ffma2(va, w01, aA0); aA1 = ffma2(va, w23, aA1);
        aB0 = ffma2(vb, w01, aB0); aB1 = ffma2(vb, w23, aB1);
    }
    float2 A0 = upk2(aA0), A1 = upk2(aA1), B0 = upk2(aB0), B1 = upk2(aB1);
    int nA = base + nl, nB = base + nl + 4;
    ((float4*)g_xl2)[nA * 32 + t] = make_float4(A0.x, A0.y, A1.x, A1.y);
    ((float4*)g_xl2)[nB * 32 + t] = make_float4(B0.x, B0.y, B1.x, B1.y);
    float4 a = ((const float4*)as)[t];
    float4 d = ((const float4*)ad)[t];
    float psA = A0.x * a.x + A0.y * a.y + A1.x * a.z + A1.y * a.w;
    float pdA = A0.x * d.x + A0.y * d.y + A1.x * d.z + A1.y * d.w;
    float psB = B0.x * a.x + B0.y * a.y + B1.x * a.z + B1.y * a.w;
    float pdB = B0.x * d.x + B0.y * d.y + B1.x * d.z + B1.y * d.w;
    #pragma unroll
    for (int o = 1; o < 32; o <<= 1) {
        psA += __shfl_xor_sync(0xffffffffu, psA, o);
        pdA += __shfl_xor_sync(0xffffffffu, pdA, o);
        psB += __shfl_xor_sync(0xffffffffu, psB, o);
        pdB += __shfl_xor_sync(0xffffffffu, pdB, o);
    }
    if (t == 0) {
        g_as2[nA] = psA; g_ad2[nA] = pdA;
        g_as2[nB] = psB; g_ad2[nB] = pdB;
    }
}

// ---------------- layer 2 aggregation + ELU + pooled accumulation ----------------
__global__ void k_agg2(const float* __restrict__ b2, const void* __restrict__ batch) {
    int n = blockIdx.x * 8 + (threadIdx.x >> 5);
    int lane = threadIdx.x & 31;
    float adv = g_ad2[n];
    float s = 0.f;
    unsigned long long axy = 0, azw = 0;
    int beg = g_off[n], end = g_off[n + 1];
    const ulonglong2* X = (const ulonglong2*)g_xl2;   // 16 B elem; row = 32 elems
    int j = beg;
    for (; j + 1 < end; j += 2) {
        int sa = g_srcs[j], sb = g_srcs[j + 1];
        float ea = g_as2[sa], eb = g_as2[sb];
        ulonglong2 va = X[sa * 32 + lane];
        ulonglong2 vb = X[sb * 32 + lane];
        ea += adv; ea = ea > 0.f ? ea : 0.2f * ea;
        eb += adv; eb = eb > 0.f ? eb : 0.2f * eb;
        float pa = __expf(ea), pb = __expf(eb);
        s += pa + pb;
        unsigned long long pa2 = pk2(pa, pa), pb2 = pk2(pb, pb);
        axy = ffma2(pa2, va.x, axy); azw = ffma2(pa2, va.y, azw);
        axy = ffma2(pb2, vb.x, axy); azw = ffma2(pb2, vb.y, azw);
    }
    if (j < end) {
        int sa = g_srcs[j];
        float ea = g_as2[sa] + adv; ea = ea > 0.f ? ea : 0.2f * ea;
        float pa = __expf(ea);
        s += pa;
        ulonglong2 va = X[sa * 32 + lane];
        unsigned long long pa2 = pk2(pa, pa);
        axy = ffma2(pa2, va.x, axy); azw = ffma2(pa2, va.y, azw);
    }
    float inv = 1.f / s;
    float2 xy = upk2(axy), zw = upk2(azw);
    float4 bb = ((const float4*)b2)[lane];
    float v0 = xy.x * inv + bb.x; v0 = v0 > 0.f ? v0 : (__expf(v0) - 1.f);
    float v1 = xy.y * inv + bb.y; v1 = v1 > 0.f ? v1 : (__expf(v1) - 1.f);
    float v2 = zw.x * inv + bb.z; v2 = v2 > 0.f ? v2 : (__expf(v2) - 1.f);
    float v3 = zw.y * inv + bb.w; v3 = v3 > 0.f ? v3 : (__expf(v3) - 1.f);
    int b = idx_at(batch, n);
    float* pp = &g_pool[b * 128 + lane * 4];
    atomicAdd(pp + 0, v0);
    atomicAdd(pp + 1, v1);
    atomicAdd(pp + 2, v2);
    atomicAdd(pp + 3, v3);
    if (lane == 0) atomicAdd(&g_cnt[b], 1);
}

// ---------------- final: mean pool -> out ----------------
__global__ void k_final(float* __restrict__ out) {
    int i = blockIdx.x * 256 + threadIdx.x;
    if (i < NG * 128) {
        int g = i >> 7;
        out[i] = g_pool[i] / fmaxf((float)g_cnt[g], 1.f);
    }
}

extern "C" void kernel_launch(void* const* d_in, const int* in_sizes, int n_in,
                              void* d_out, int out_size) {
    const float* x   = (const float*)d_in[0];
    const void*  ei  = d_in[1];
    const void*  bat = d_in[2];
    const float* W1  = (const float*)d_in[3];
    const float* as1 = (const float*)d_in[4];
    const float* ad1 = (const float*)d_in[5];
    const float* b1  = (const float*)d_in[6];
    const float* W2  = (const float*)d_in[7];
    const float* as2 = (const float*)d_in[8];
    const float* ad2 = (const float*)d_in[9];
    const float* b2  = (const float*)d_in[10];
    float* out = (float*)d_out;

    k_zero<<<NSB, 256>>>((const int*)ei);
    k_hist<<<(NE + 255) / 256, 256>>>(ei);
    k_scan1<<<NSB, 256>>>();
    k_scan2<<<1, 256>>>();
    k_scan3<<<NSB, 256>>>();
    k_fill<<<(ET + 255) / 256, 256>>>(ei);
    k_gemm1<<<NN / 16, 128>>>(x, W1, as1, ad1);
    k_agg1<<<NN / 8, 256>>>(b1);
    k_gemm2<<<NN / 8, 128>>>(W2, as2, ad2);
    k_agg2<<<NN / 8, 256>>>(b2, bat);
    k_final<<<32, 256>>>(out);
}

// round 4
// speedup vs baseline: 1.4029x; 1.0492x over previous
#include <cuda_runtime.h>
#include <cuda_fp16.h>

#define NN 50000
#define NE 1600000
#define NG 64
#define NSB ((NN + 255) / 256)   // 196 scan blocks

// ---------------- scratch (static device globals; no allocation) ----------------
__device__ __align__(16) __half g_xl1h[NN * 64];
__device__ __align__(16) __half g_xl2h[NN * 128];
__device__ float g_as1[NN * 2];
__device__ float g_ad1[NN * 2];
__device__ float g_h1[NN * 64];
__device__ float g_as2[NN];
__device__ float g_ad2[NN];
__device__ int   g_deg[NN];
__device__ int   g_off[NN + 1];
__device__ int   g_cur[NN];
__device__ int   g_srcs[NE + NN];
__device__ int   g_bsum[NSB];
__device__ int   g_boff[NSB];
__device__ float g_pool[NG * 128];
__device__ int   g_cnt[NG];
__device__ int   g_is64;

// ---------------- f32x2 packed helpers ----------------
__device__ __forceinline__ unsigned long long pk2(float x, float y) {
    unsigned long long r;
    asm("mov.b64 %0,{%1,%2};" : "=l"(r) : "f"(x), "f"(y));
    return r;
}
__device__ __forceinline__ float2 upk2(unsigned long long v) {
    float x, y;
    asm("mov.b64 {%0,%1},%2;" : "=f"(x), "=f"(y) : "l"(v));
    return make_float2(x, y);
}
__device__ __forceinline__ unsigned long long ffma2(unsigned long long a,
                                                    unsigned long long b,
                                                    unsigned long long c) {
    unsigned long long d;
    asm("fma.rn.f32x2 %0,%1,%2,%3;" : "=l"(d) : "l"(a), "l"(b), "l"(c));
    return d;
}

__device__ __forceinline__ int idx_at(const void* p, int i) {
    if (g_is64) return (int)((const long long*)p)[i];
    return ((const int*)p)[i];
}

// ---------------- zero + dtype detect ----------------
__global__ void k_zero(const int* __restrict__ ei32) {
    int i = blockIdx.x * 256 + threadIdx.x;
    if (i < NN) g_deg[i] = 0;
    if (i < NG * 128) g_pool[i] = 0.f;
    if (i < NG) g_cnt[i] = 0;
    if (i == 0) {
        int ok = 1;
        for (int k = 0; k < 64; k++)
            if (ei32[2 * k + 1] != 0) ok = 0;
        g_is64 = ok;
    }
}

// ---------------- CSR build ----------------
// 2 edges per thread, vector index loads.
__global__ void k_hist(const void* __restrict__ ei) {
    int t = blockIdx.x * 256 + threadIdx.x;      // pair index
    if (t >= NE / 2) return;
    int d0, d1;
    if (g_is64) {
        longlong2 v = ((const longlong2*)((const long long*)ei + NE))[t];
        d0 = (int)v.x; d1 = (int)v.y;
    } else {
        int2 v = ((const int2*)((const int*)ei + NE))[t];
        d0 = v.x; d1 = v.y;
    }
    atomicAdd(&g_deg[d0], 1);
    atomicAdd(&g_deg[d1], 1);
}

__global__ void k_scan1() {
    int t = threadIdx.x, i = blockIdx.x * 256 + t;
    int v = (i < NN) ? (g_deg[i] + 1) : 0;
    #pragma unroll
    for (int o = 16; o > 0; o >>= 1) v += __shfl_xor_sync(0xffffffffu, v, o);
    __shared__ int ws[8];
    if ((t & 31) == 0) ws[t >> 5] = v;
    __syncthreads();
    if (t == 0) {
        int s = 0;
        #pragma unroll
        for (int w = 0; w < 8; w++) s += ws[w];
        g_bsum[blockIdx.x] = s;
    }
}

__global__ void k_scan2() {
    __shared__ int sh[256];
    int t = threadIdx.x;
    int v = (t < NSB) ? g_bsum[t] : 0;
    sh[t] = v;
    __syncthreads();
    for (int o = 1; o < 256; o <<= 1) {
        int u = (t >= o) ? sh[t - o] : 0;
        __syncthreads();
        sh[t] += u;
        __syncthreads();
    }
    if (t < NSB) g_boff[t] = sh[t] - v;
    if (t == NSB - 1) g_off[NN] = sh[t];
}

__global__ void k_scan3() {
    int t = threadIdx.x, lane = t & 31, wid = t >> 5;
    int i = blockIdx.x * 256 + t;
    int v = (i < NN) ? (g_deg[i] + 1) : 0;
    int x = v;
    #pragma unroll
    for (int o = 1; o < 32; o <<= 1) {
        int u = __shfl_up_sync(0xffffffffu, x, o);
        if (lane >= o) x += u;
    }
    __shared__ int ws[8];
    if (lane == 31) ws[wid] = x;
    __syncthreads();
    if (wid == 0 && lane < 8) {
        int w = ws[lane];
        int y = w;
        #pragma unroll
        for (int o = 1; o < 8; o <<= 1) {
            int u = __shfl_up_sync(0xffu, y, o);
            if (lane >= o) y += u;
        }
        ws[lane] = y - w;
    }
    __syncthreads();
    int excl = x - v + ws[wid] + g_boff[blockIdx.x];
    if (i < NN) { g_off[i] = excl; g_cur[i] = excl; }
}

// pairs of edges first, then self loops
__global__ void k_fill(const void* __restrict__ ei) {
    int t = blockIdx.x * 256 + threadIdx.x;
    if (t < NE / 2) {
        int s0, s1, d0, d1;
        if (g_is64) {
            longlong2 sv = ((const longlong2*)ei)[t];
            longlong2 dv = ((const longlong2*)((const long long*)ei + NE))[t];
            s0 = (int)sv.x; s1 = (int)sv.y; d0 = (int)dv.x; d1 = (int)dv.y;
        } else {
            int2 sv = ((const int2*)ei)[t];
            int2 dv = ((const int2*)((const int*)ei + NE))[t];
            s0 = sv.x; s1 = sv.y; d0 = dv.x; d1 = dv.y;
        }
        g_srcs[atomicAdd(&g_cur[d0], 1)] = s0;
        g_srcs[atomicAdd(&g_cur[d1], 1)] = s1;
    } else {
        int n = t - NE / 2;
        if (n < NN) g_srcs[atomicAdd(&g_cur[n], 1)] = n;
    }
}

// ---------------- layer 1 GEMM: xl1 = x @ W1 (+ attention scores), fp16 out -----
// 128 threads = 8 node-slots x 16 col-groups; each thread: 2 nodes x 4 cols, f32x2.
__global__ void k_gemm1(const float* __restrict__ x, const float* __restrict__ W1,
                        const float* __restrict__ as, const float* __restrict__ ad) {
    __shared__ float xsh[16 * 128];
    int tid = threadIdx.x;
    int base = blockIdx.x * 16;
    {
        float4* d4 = (float4*)xsh;
        const float4* s4 = (const float4*)(x + (long)base * 128);
        for (int i = tid; i < 512; i += 128) d4[i] = s4[i];
    }
    __syncthreads();
    int nl = tid >> 4, t4 = tid & 15;
    const float4* W4 = (const float4*)W1;
    unsigned long long aA0 = 0, aA1 = 0, aB0 = 0, aB1 = 0;
    const float* xa = &xsh[nl * 128];
    const float* xb = &xsh[(nl + 8) * 128];
    #pragma unroll 4
    for (int k = 0; k < 128; k++) {
        float4 w = W4[k * 16 + t4];
        unsigned long long w01 = pk2(w.x, w.y), w23 = pk2(w.z, w.w);
        unsigned long long va = pk2(xa[k], xa[k]);
        unsigned long long vb = pk2(xb[k], xb[k]);
        aA0 = ffma2(va, w01, aA0); aA1 = ffma2(va, w23, aA1);
        aB0 = ffma2(vb, w01, aB0); aB1 = ffma2(vb, w23, aB1);
    }
    float2 A0 = upk2(aA0), A1 = upk2(aA1), B0 = upk2(aB0), B1 = upk2(aB1);
    int nA = base + nl, nB = base + nl + 8;
    {   // fp16 rows for the gather (cols 4*t4 .. 4*t4+3)
        __half2 a01 = __floats2half2_rn(A0.x, A0.y);
        __half2 a23 = __floats2half2_rn(A1.x, A1.y);
        __half2 b01 = __floats2half2_rn(B0.x, B0.y);
        __half2 b23 = __floats2half2_rn(B1.x, B1.y);
        uint2 pa, pb;
        pa.x = *(unsigned*)&a01; pa.y = *(unsigned*)&a23;
        pb.x = *(unsigned*)&b01; pb.y = *(unsigned*)&b23;
        ((uint2*)g_xl1h)[nA * 16 + t4] = pa;
        ((uint2*)g_xl1h)[nB * 16 + t4] = pb;
    }
    float4 a = ((const float4*)as)[t4];
    float4 d = ((const float4*)ad)[t4];
    float psA = A0.x * a.x + A0.y * a.y + A1.x * a.z + A1.y * a.w;
    float pdA = A0.x * d.x + A0.y * d.y + A1.x * d.z + A1.y * d.w;
    float psB = B0.x * a.x + B0.y * a.y + B1.x * a.z + B1.y * a.w;
    float pdB = B0.x * d.x + B0.y * d.y + B1.x * d.z + B1.y * d.w;
    #pragma unroll
    for (int o = 1; o < 8; o <<= 1) {
        psA += __shfl_xor_sync(0xffffffffu, psA, o);
        pdA += __shfl_xor_sync(0xffffffffu, pdA, o);
        psB += __shfl_xor_sync(0xffffffffu, psB, o);
        pdB += __shfl_xor_sync(0xffffffffu, pdB, o);
    }
    if ((t4 & 7) == 0) {
        int h = t4 >> 3;
        g_as1[nA * 2 + h] = psA;  g_ad1[nA * 2 + h] = pdA;
        g_as1[nB * 2 + h] = psB;  g_ad1[nB * 2 + h] = pdB;
    }
}

// ---------------- layer 1 aggregation ----------------
// one warp per node; lane owns cols (2l, 2l+1) — both in head l>>4.
__global__ void k_agg1(const float* __restrict__ b1) {
    int n = blockIdx.x * 8 + (threadIdx.x >> 5);
    int lane = threadIdx.x & 31;
    float2 adv2 = ((const float2*)g_ad1)[n];
    bool h0 = lane < 16;
    float adv = h0 ? adv2.x : adv2.y;
    float s = 0.f;
    unsigned long long acc = 0;
    int beg = g_off[n], end = g_off[n + 1];
    const __half2* X = (const __half2*)g_xl1h;   // row = 32 half2
    int j = beg;
    for (; j + 1 < end; j += 2) {
        int sa = g_srcs[j], sb = g_srcs[j + 1];
        float2 ea2 = ((const float2*)g_as1)[sa];
        float2 eb2 = ((const float2*)g_as1)[sb];
        __half2 xa = X[sa * 32 + lane];
        __half2 xb = X[sb * 32 + lane];
        float ea = (h0 ? ea2.x : ea2.y) + adv; ea = ea > 0.f ? ea : 0.2f * ea;
        float eb = (h0 ? eb2.x : eb2.y) + adv; eb = eb > 0.f ? eb : 0.2f * eb;
        float pa = __expf(ea), pb = __expf(eb);
        s += pa + pb;
        float2 fa = __half22float2(xa), fb = __half22float2(xb);
        acc = ffma2(pk2(pa, pa), pk2(fa.x, fa.y), acc);
        acc = ffma2(pk2(pb, pb), pk2(fb.x, fb.y), acc);
    }
    if (j < end) {
        int sa = g_srcs[j];
        float2 ea2 = ((const float2*)g_as1)[sa];
        __half2 xa = X[sa * 32 + lane];
        float ea = (h0 ? ea2.x : ea2.y) + adv; ea = ea > 0.f ? ea : 0.2f * ea;
        float pa = __expf(ea);
        s += pa;
        float2 fa = __half22float2(xa);
        acc = ffma2(pk2(pa, pa), pk2(fa.x, fa.y), acc);
    }
    float inv = 1.f / s;
    float2 u = upk2(acc);
    float2 bb = ((const float2*)b1)[lane];
    float o0 = u.x * inv + bb.x;
    float o1 = u.y * inv + bb.y;
    o0 = o0 > 0.f ? o0 : (__expf(o0) - 1.f);
    o1 = o1 > 0.f ? o1 : (__expf(o1) - 1.f);
    ((float2*)g_h1)[n * 32 + lane] = make_float2(o0, o1);
}

// ---------------- layer 2 GEMM: xl2 = h1 @ W2 (+ scores), fp16 out ----------------
__global__ void k_gemm2(const float* __restrict__ W2, const float* __restrict__ as,
                        const float* __restrict__ ad) {
    __shared__ float hsh[8 * 64];
    int tid = threadIdx.x;
    int base = blockIdx.x * 8;
    {
        float4* d4 = (float4*)hsh;
        const float4* s4 = (const float4*)(g_h1 + (long)base * 64);
        if (tid < 128) d4[tid] = s4[tid];
    }
    __syncthreads();
    int nl = tid >> 5, t = tid & 31;
    const float4* W4 = (const float4*)W2;
    unsigned long long aA0 = 0, aA1 = 0, aB0 = 0, aB1 = 0;
    const float* xa = &hsh[nl * 64];
    const float* xb = &hsh[(nl + 4) * 64];
    #pragma unroll 4
    for (int k = 0; k < 64; k++) {
        float4 w = W4[k * 32 + t];
        unsigned long long w01 = pk2(w.x, w.y), w23 = pk2(w.z, w.w);
        unsigned long long va = pk2(xa[k], xa[k]);
        unsigned long long vb = pk2(xb[k], xb[k]);
        aA0 = ffma2(va, w01, aA0); aA1 = ffma2(va, w23, aA1);
        aB0 = ffma2(vb, w01, aB0); aB1 = ffma2(vb, w23, aB1);
    }
    float2 A0 = upk2(aA0), A1 = upk2(aA1), B0 = upk2(aB0), B1 = upk2(aB1);
    int nA = base + nl, nB = base + nl + 4;
    {   // fp16 rows (cols 4t..4t+3); row = 32 uint2
        __half2 a01 = __floats2half2_rn(A0.x, A0.y);
        __half2 a23 = __floats2half2_rn(A1.x, A1.y);
        __half2 b01 = __floats2half2_rn(B0.x, B0.y);
        __half2 b23 = __floats2half2_rn(B1.x, B1.y);
        uint2 pa, pb;
        pa.x = *(unsigned*)&a01; pa.y = *(unsigned*)&a23;
        pb.x = *(unsigned*)&b01; pb.y = *(unsigned*)&b23;
        ((uint2*)g_xl2h)[nA * 32 + t] = pa;
        ((uint2*)g_xl2h)[nB * 32 + t] = pb;
    }
    float4 a = ((const float4*)as)[t];
    float4 d = ((const float4*)ad)[t];
    float psA = A0.x * a.x + A0.y * a.y + A1.x * a.z + A1.y * a.w;
    float pdA = A0.x * d.x + A0.y * d.y + A1.x * d.z + A1.y * d.w;
    float psB = B0.x * a.x + B0.y * a.y + B1.x * a.z + B1.y * a.w;
    float pdB = B0.x * d.x + B0.y * d.y + B1.x * d.z + B1.y * d.w;
    #pragma unroll
    for (int o = 1; o < 32; o <<= 1) {
        psA += __shfl_xor_sync(0xffffffffu, psA, o);
        pdA += __shfl_xor_sync(0xffffffffu, pdA, o);
        psB += __shfl_xor_sync(0xffffffffu, psB, o);
        pdB += __shfl_xor_sync(0xffffffffu, pdB, o);
    }
    if (t == 0) {
        g_as2[nA] = psA; g_ad2[nA] = pdA;
        g_as2[nB] = psB; g_ad2[nB] = pdB;
    }
}

// ---------------- layer 2 aggregation + ELU + pooled accumulation ----------------
// lane owns cols 4l..4l+3 (uint2 = 2 half2 per edge).
__global__ void k_agg2(const float* __restrict__ b2, const void* __restrict__ batch) {
    int n = blockIdx.x * 8 + (threadIdx.x >> 5);
    int lane = threadIdx.x & 31;
    float adv = g_ad2[n];
    float s = 0.f;
    unsigned long long axy = 0, azw = 0;
    int beg = g_off[n], end = g_off[n + 1];
    const uint2* X = (const uint2*)g_xl2h;   // row = 32 uint2
    int j = beg;
    for (; j + 1 < end; j += 2) {
        int sa = g_srcs[j], sb = g_srcs[j + 1];
        float ea = g_as2[sa], eb = g_as2[sb];
        uint2 va = X[sa * 32 + lane];
        uint2 vb = X[sb * 32 + lane];
        ea += adv; ea = ea > 0.f ? ea : 0.2f * ea;
        eb += adv; eb = eb > 0.f ? eb : 0.2f * eb;
        float pa = __expf(ea), pb = __expf(eb);
        s += pa + pb;
        float2 fa0 = __half22float2(*(const __half2*)&va.x);
        float2 fa1 = __half22float2(*(const __half2*)&va.y);
        float2 fb0 = __half22float2(*(const __half2*)&vb.x);
        float2 fb1 = __half22float2(*(const __half2*)&vb.y);
        unsigned long long pa2 = pk2(pa, pa), pb2 = pk2(pb, pb);
        axy = ffma2(pa2, pk2(fa0.x, fa0.y), axy);
        azw = ffma2(pa2, pk2(fa1.x, fa1.y), azw);
        axy = ffma2(pb2, pk2(fb0.x, fb0.y), axy);
        azw = ffma2(pb2, pk2(fb1.x, fb1.y), azw);
    }
    if (j < end) {
        int sa = g_srcs[j];
        float ea = g_as2[sa] + adv; ea = ea > 0.f ? ea : 0.2f * ea;
        float pa = __expf(ea);
        s += pa;
        uint2 va = X[sa * 32 + lane];
        float2 fa0 = __half22float2(*(const __half2*)&va.x);
        float2 fa1 = __half22float2(*(const __half2*)&va.y);
        unsigned long long pa2 = pk2(pa, pa);
        axy = ffma2(pa2, pk2(fa0.x, fa0.y), axy);
        azw = ffma2(pa2, pk2(fa1.x, fa1.y), azw);
    }
    float inv = 1.f / s;
    float2 xy = upk2(axy), zw = upk2(azw);
    float4 bb = ((const float4*)b2)[lane];
    float v0 = xy.x * inv + bb.x; v0 = v0 > 0.f ? v0 : (__expf(v0) - 1.f);
    float v1 = xy.y * inv + bb.y; v1 = v1 > 0.f ? v1 : (__expf(v1) - 1.f);
    float v2 = zw.x * inv + bb.z; v2 = v2 > 0.f ? v2 : (__expf(v2) - 1.f);
    float v3 = zw.y * inv + bb.w; v3 = v3 > 0.f ? v3 : (__expf(v3) - 1.f);
    int b = idx_at(batch, n);
    float* pp = &g_pool[b * 128 + lane * 4];
    atomicAdd(pp + 0, v0);
    atomicAdd(pp + 1, v1);
    atomicAdd(pp + 2, v2);
    atomicAdd(pp + 3, v3);
    if (lane == 0) atomicAdd(&g_cnt[b], 1);
}

// ---------------- final: mean pool -> out ----------------
__global__ void k_final(float* __restrict__ out) {
    int i = blockIdx.x * 256 + threadIdx.x;
    if (i < NG * 128) {
        int g = i >> 7;
        out[i] = g_pool[i] / fmaxf((float)g_cnt[g], 1.f);
    }
}

extern "C" void kernel_launch(void* const* d_in, const int* in_sizes, int n_in,
                              void* d_out, int out_size) {
    const float* x   = (const float*)d_in[0];
    const void*  ei  = d_in[1];
    const void*  bat = d_in[2];
    const float* W1  = (const float*)d_in[3];
    const float* as1 = (const float*)d_in[4];
    const float* ad1 = (const float*)d_in[5];
    const float* b1  = (const float*)d_in[6];
    const float* W2  = (const float*)d_in[7];
    const float* as2 = (const float*)d_in[8];
    const float* ad2 = (const float*)d_in[9];
    const float* b2  = (const float*)d_in[10];
    float* out = (float*)d_out;

    k_zero<<<NSB, 256>>>((const int*)ei);
    k_hist<<<(NE / 2 + 255) / 256, 256>>>(ei);
    k_scan1<<<NSB, 256>>>();
    k_scan2<<<1, 256>>>();
    k_scan3<<<NSB, 256>>>();
    k_fill<<<(NE / 2 + NN + 255) / 256, 256>>>(ei);
    k_gemm1<<<NN / 16, 128>>>(x, W1, as1, ad1);
    k_agg1<<<NN / 8, 256>>>(b1);
    k_gemm2<<<NN / 8, 128>>>(W2, as2, ad2);
    k_agg2<<<NN / 8, 256>>>(b2, bat);
    k_final<<<32, 256>>>(out);
}

// round 5
// speedup vs baseline: 1.5937x; 1.1361x over previous
#include <cuda_runtime.h>
#include <cuda_fp16.h>

#define NN 50000
#define NE 1600000
#define NG 64
#define NSB ((NN + 255) / 256)   // 196 scan blocks

// ---------------- scratch (static device globals; no allocation) ----------------
__device__ __align__(16) __half g_xl1h[NN * 64];
__device__ __align__(16) __half g_xl2h[NN * 128];
__device__ float g_as1[NN * 2];
__device__ float g_ad1[NN * 2];
__device__ float g_h1[NN * 64];
__device__ float g_as2[NN];
__device__ float g_ad2[NN];
__device__ int   g_deg[NN];
__device__ int   g_off[NN + 1];
__device__ int   g_cur[NN];
__device__ int   g_srcs[NE + NN];
__device__ int   g_bsum[NSB];
__device__ int   g_boff[NSB];
__device__ float g_pool[NG * 128];
__device__ int   g_cnt[NG];
__device__ int   g_is64;

// ---------------- f32x2 packed helpers ----------------
__device__ __forceinline__ unsigned long long pk2(float x, float y) {
    unsigned long long r;
    asm("mov.b64 %0,{%1,%2};" : "=l"(r) : "f"(x), "f"(y));
    return r;
}
__device__ __forceinline__ float2 upk2(unsigned long long v) {
    float x, y;
    asm("mov.b64 {%0,%1},%2;" : "=f"(x), "=f"(y) : "l"(v));
    return make_float2(x, y);
}
__device__ __forceinline__ unsigned long long ffma2(unsigned long long a,
                                                    unsigned long long b,
                                                    unsigned long long c) {
    unsigned long long d;
    asm("fma.rn.f32x2 %0,%1,%2,%3;" : "=l"(d) : "l"(a), "l"(b), "l"(c));
    return d;
}

__device__ __forceinline__ int idx_at(const void* p, int i) {
    if (g_is64) return (int)((const long long*)p)[i];
    return ((const int*)p)[i];
}
__device__ __forceinline__ float lrelu(float e) { return e > 0.f ? e : 0.2f * e; }

// ---------------- zero + dtype detect ----------------
__global__ void k_zero(const int* __restrict__ ei32) {
    int i = blockIdx.x * 256 + threadIdx.x;
    if (i < NN) g_deg[i] = 0;
    if (i < NG * 128) g_pool[i] = 0.f;
    if (i < NG) g_cnt[i] = 0;
    if (i == 0) {
        int ok = 1;
        for (int k = 0; k < 64; k++)
            if (ei32[2 * k + 1] != 0) ok = 0;
        g_is64 = ok;
    }
}

// ---------------- CSR build ----------------
__global__ void k_hist(const void* __restrict__ ei) {
    int t = blockIdx.x * 256 + threadIdx.x;      // pair index
    if (t >= NE / 2) return;
    int d0, d1;
    if (g_is64) {
        longlong2 v = ((const longlong2*)((const long long*)ei + NE))[t];
        d0 = (int)v.x; d1 = (int)v.y;
    } else {
        int2 v = ((const int2*)((const int*)ei + NE))[t];
        d0 = v.x; d1 = v.y;
    }
    atomicAdd(&g_deg[d0], 1);
    atomicAdd(&g_deg[d1], 1);
}

__global__ void k_scan1() {
    int t = threadIdx.x, i = blockIdx.x * 256 + t;
    int v = (i < NN) ? (g_deg[i] + 1) : 0;
    #pragma unroll
    for (int o = 16; o > 0; o >>= 1) v += __shfl_xor_sync(0xffffffffu, v, o);
    __shared__ int ws[8];
    if ((t & 31) == 0) ws[t >> 5] = v;
    __syncthreads();
    if (t == 0) {
        int s = 0;
        #pragma unroll
        for (int w = 0; w < 8; w++) s += ws[w];
        g_bsum[blockIdx.x] = s;
    }
}

__global__ void k_scan2() {
    __shared__ int sh[256];
    int t = threadIdx.x;
    int v = (t < NSB) ? g_bsum[t] : 0;
    sh[t] = v;
    __syncthreads();
    for (int o = 1; o < 256; o <<= 1) {
        int u = (t >= o) ? sh[t - o] : 0;
        __syncthreads();
        sh[t] += u;
        __syncthreads();
    }
    if (t < NSB) g_boff[t] = sh[t] - v;
    if (t == NSB - 1) g_off[NN] = sh[t];
}

// scan3 also pre-seeds the self-loop as the first entry of each segment.
__global__ void k_scan3() {
    int t = threadIdx.x, lane = t & 31, wid = t >> 5;
    int i = blockIdx.x * 256 + t;
    int v = (i < NN) ? (g_deg[i] + 1) : 0;
    int x = v;
    #pragma unroll
    for (int o = 1; o < 32; o <<= 1) {
        int u = __shfl_up_sync(0xffffffffu, x, o);
        if (lane >= o) x += u;
    }
    __shared__ int ws[8];
    if (lane == 31) ws[wid] = x;
    __syncthreads();
    if (wid == 0 && lane < 8) {
        int w = ws[lane];
        int y = w;
        #pragma unroll
        for (int o = 1; o < 8; o <<= 1) {
            int u = __shfl_up_sync(0xffu, y, o);
            if (lane >= o) y += u;
        }
        ws[lane] = y - w;
    }
    __syncthreads();
    int excl = x - v + ws[wid] + g_boff[blockIdx.x];
    if (i < NN) {
        g_off[i] = excl;
        g_srcs[excl] = i;       // self loop occupies slot 0
        g_cur[i] = excl + 1;
    }
}

// real edges only (self loops already placed)
__global__ void k_fill(const void* __restrict__ ei) {
    int t = blockIdx.x * 256 + threadIdx.x;
    if (t >= NE / 2) return;
    int s0, s1, d0, d1;
    if (g_is64) {
        longlong2 sv = ((const longlong2*)ei)[t];
        longlong2 dv = ((const longlong2*)((const long long*)ei + NE))[t];
        s0 = (int)sv.x; s1 = (int)sv.y; d0 = (int)dv.x; d1 = (int)dv.y;
    } else {
        int2 sv = ((const int2*)ei)[t];
        int2 dv = ((const int2*)((const int*)ei + NE))[t];
        s0 = sv.x; s1 = sv.y; d0 = dv.x; d1 = dv.y;
    }
    g_srcs[atomicAdd(&g_cur[d0], 1)] = s0;
    g_srcs[atomicAdd(&g_cur[d1], 1)] = s1;
}

// ---------------- layer 1 GEMM: xl1 = x @ W1 (+ attention scores), fp16 out -----
__global__ void k_gemm1(const float* __restrict__ x, const float* __restrict__ W1,
                        const float* __restrict__ as, const float* __restrict__ ad) {
    __shared__ float xsh[16 * 128];
    int tid = threadIdx.x;
    int base = blockIdx.x * 16;
    {
        float4* d4 = (float4*)xsh;
        const float4* s4 = (const float4*)(x + (long)base * 128);
        for (int i = tid; i < 512; i += 128) d4[i] = s4[i];
    }
    __syncthreads();
    int nl = tid >> 4, t4 = tid & 15;
    const float4* W4 = (const float4*)W1;
    unsigned long long aA0 = 0, aA1 = 0, aB0 = 0, aB1 = 0;
    const float* xa = &xsh[nl * 128];
    const float* xb = &xsh[(nl + 8) * 128];
    #pragma unroll 4
    for (int k = 0; k < 128; k++) {
        float4 w = W4[k * 16 + t4];
        unsigned long long w01 = pk2(w.x, w.y), w23 = pk2(w.z, w.w);
        unsigned long long va = pk2(xa[k], xa[k]);
        unsigned long long vb = pk2(xb[k], xb[k]);
        aA0 = ffma2(va, w01, aA0); aA1 = ffma2(va, w23, aA1);
        aB0 = ffma2(vb, w01, aB0); aB1 = ffma2(vb, w23, aB1);
    }
    float2 A0 = upk2(aA0), A1 = upk2(aA1), B0 = upk2(aB0), B1 = upk2(aB1);
    int nA = base + nl, nB = base + nl + 8;
    {
        __half2 a01 = __floats2half2_rn(A0.x, A0.y);
        __half2 a23 = __floats2half2_rn(A1.x, A1.y);
        __half2 b01 = __floats2half2_rn(B0.x, B0.y);
        __half2 b23 = __floats2half2_rn(B1.x, B1.y);
        uint2 pa, pb;
        pa.x = *(unsigned*)&a01; pa.y = *(unsigned*)&a23;
        pb.x = *(unsigned*)&b01; pb.y = *(unsigned*)&b23;
        ((uint2*)g_xl1h)[nA * 16 + t4] = pa;
        ((uint2*)g_xl1h)[nB * 16 + t4] = pb;
    }
    float4 a = ((const float4*)as)[t4];
    float4 d = ((const float4*)ad)[t4];
    float psA = A0.x * a.x + A0.y * a.y + A1.x * a.z + A1.y * a.w;
    float pdA = A0.x * d.x + A0.y * d.y + A1.x * d.z + A1.y * d.w;
    float psB = B0.x * a.x + B0.y * a.y + B1.x * a.z + B1.y * a.w;
    float pdB = B0.x * d.x + B0.y * d.y + B1.x * d.z + B1.y * d.w;
    #pragma unroll
    for (int o = 1; o < 8; o <<= 1) {
        psA += __shfl_xor_sync(0xffffffffu, psA, o);
        pdA += __shfl_xor_sync(0xffffffffu, pdA, o);
        psB += __shfl_xor_sync(0xffffffffu, psB, o);
        pdB += __shfl_xor_sync(0xffffffffu, pdB, o);
    }
    if ((t4 & 7) == 0) {
        int h = t4 >> 3;
        g_as1[nA * 2 + h] = psA;  g_ad1[nA * 2 + h] = pdA;
        g_as1[nB * 2 + h] = psB;  g_ad1[nB * 2 + h] = pdB;
    }
}

// ---------------- layer 1 aggregation: 1 warp/node, 4-edge pipelined ------------
__global__ void k_agg1(const float* __restrict__ b1) {
    int n = blockIdx.x * 8 + (threadIdx.x >> 5);
    int lane = threadIdx.x & 31;
    float2 adv2 = ((const float2*)g_ad1)[n];
    bool h0 = lane < 16;
    float adv = h0 ? adv2.x : adv2.y;
    float s = 0.f;
    unsigned long long acc = 0;
    int beg = g_off[n], end = g_off[n + 1];
    const __half2* X = (const __half2*)g_xl1h;   // row = 32 half2
    int j = beg;
    for (; j + 3 < end; j += 4) {
        int s0 = g_srcs[j], s1 = g_srcs[j + 1], s2 = g_srcs[j + 2], s3 = g_srcs[j + 3];
        float2 q0 = ((const float2*)g_as1)[s0];
        float2 q1 = ((const float2*)g_as1)[s1];
        float2 q2 = ((const float2*)g_as1)[s2];
        float2 q3 = ((const float2*)g_as1)[s3];
        __half2 x0 = X[s0 * 32 + lane];
        __half2 x1 = X[s1 * 32 + lane];
        __half2 x2 = X[s2 * 32 + lane];
        __half2 x3 = X[s3 * 32 + lane];
        float p0 = __expf(lrelu((h0 ? q0.x : q0.y) + adv));
        float p1 = __expf(lrelu((h0 ? q1.x : q1.y) + adv));
        float p2 = __expf(lrelu((h0 ? q2.x : q2.y) + adv));
        float p3 = __expf(lrelu((h0 ? q3.x : q3.y) + adv));
        s += (p0 + p1) + (p2 + p3);
        float2 f0 = __half22float2(x0), f1 = __half22float2(x1);
        float2 f2 = __half22float2(x2), f3 = __half22float2(x3);
        acc = ffma2(pk2(p0, p0), pk2(f0.x, f0.y), acc);
        acc = ffma2(pk2(p1, p1), pk2(f1.x, f1.y), acc);
        acc = ffma2(pk2(p2, p2), pk2(f2.x, f2.y), acc);
        acc = ffma2(pk2(p3, p3), pk2(f3.x, f3.y), acc);
    }
    for (; j < end; j++) {
        int s0 = g_srcs[j];
        float2 q0 = ((const float2*)g_as1)[s0];
        __half2 x0 = X[s0 * 32 + lane];
        float p0 = __expf(lrelu((h0 ? q0.x : q0.y) + adv));
        s += p0;
        float2 f0 = __half22float2(x0);
        acc = ffma2(pk2(p0, p0), pk2(f0.x, f0.y), acc);
    }
    float inv = 1.f / s;
    float2 u = upk2(acc);
    float2 bb = ((const float2*)b1)[lane];
    float o0 = u.x * inv + bb.x;
    float o1 = u.y * inv + bb.y;
    o0 = o0 > 0.f ? o0 : (__expf(o0) - 1.f);
    o1 = o1 > 0.f ? o1 : (__expf(o1) - 1.f);
    ((float2*)g_h1)[n * 32 + lane] = make_float2(o0, o1);
}

// ---------------- layer 2 GEMM: xl2 = h1 @ W2 (+ scores), fp16 out ----------------
__global__ void k_gemm2(const float* __restrict__ W2, const float* __restrict__ as,
                        const float* __restrict__ ad) {
    __shared__ float hsh[8 * 64];
    int tid = threadIdx.x;
    int base = blockIdx.x * 8;
    {
        float4* d4 = (float4*)hsh;
        const float4* s4 = (const float4*)(g_h1 + (long)base * 64);
        if (tid < 128) d4[tid] = s4[tid];
    }
    __syncthreads();
    int nl = tid >> 5, t = tid & 31;
    const float4* W4 = (const float4*)W2;
    unsigned long long aA0 = 0, aA1 = 0, aB0 = 0, aB1 = 0;
    const float* xa = &hsh[nl * 64];
    const float* xb = &hsh[(nl + 4) * 64];
    #pragma unroll 4
    for (int k = 0; k < 64; k++) {
        float4 w = W4[k * 32 + t];
        unsigned long long w01 = pk2(w.x, w.y), w23 = pk2(w.z, w.w);
        unsigned long long va = pk2(xa[k], xa[k]);
        unsigned long long vb = pk2(xb[k], xb[k]);
        aA0 = ffma2(va, w01, aA0); aA1 = ffma2(va, w23, aA1);
        aB0 = ffma2(vb, w01, aB0); aB1 = ffma2(vb, w23, aB1);
    }
    float2 A0 = upk2(aA0), A1 = upk2(aA1), B0 = upk2(aB0), B1 = upk2(aB1);
    int nA = base + nl, nB = base + nl + 4;
    {
        __half2 a01 = __floats2half2_rn(A0.x, A0.y);
        __half2 a23 = __floats2half2_rn(A1.x, A1.y);
        __half2 b01 = __floats2half2_rn(B0.x, B0.y);
        __half2 b23 = __floats2half2_rn(B1.x, B1.y);
        uint2 pa, pb;
        pa.x = *(unsigned*)&a01; pa.y = *(unsigned*)&a23;
        pb.x = *(unsigned*)&b01; pb.y = *(unsigned*)&b23;
        ((uint2*)g_xl2h)[nA * 32 + t] = pa;
        ((uint2*)g_xl2h)[nB * 32 + t] = pb;
    }
    float4 a = ((const float4*)as)[t];
    float4 d = ((const float4*)ad)[t];
    float psA = A0.x * a.x + A0.y * a.y + A1.x * a.z + A1.y * a.w;
    float pdA = A0.x * d.x + A0.y * d.y + A1.x * d.z + A1.y * d.w;
    float psB = B0.x * a.x + B0.y * a.y + B1.x * a.z + B1.y * a.w;
    float pdB = B0.x * d.x + B0.y * d.y + B1.x * d.z + B1.y * d.w;
    #pragma unroll
    for (int o = 1; o < 32; o <<= 1) {
        psA += __shfl_xor_sync(0xffffffffu, psA, o);
        pdA += __shfl_xor_sync(0xffffffffu, pdA, o);
        psB += __shfl_xor_sync(0xffffffffu, psB, o);
        pdB += __shfl_xor_sync(0xffffffffu, pdB, o);
    }
    if (t == 0) {
        g_as2[nA] = psA; g_ad2[nA] = pdA;
        g_as2[nB] = psB; g_ad2[nB] = pdB;
    }
}

// ---------------- layer 2 aggregation: 2 warps/node, 4-edge pipelined ------------
// warp w of node owns cols [64w, 64w+64); lane holds one half2 (cols 64w+2l, +1).
__global__ void k_agg2(const float* __restrict__ b2, const void* __restrict__ batch) {
    int t = threadIdx.x;
    int n = blockIdx.x * 4 + (t >> 6);
    int w = (t >> 5) & 1;
    int lane = t & 31;
    int col = w * 32 + lane;                      // half2 index within row
    float adv = g_ad2[n];
    float s = 0.f;
    unsigned long long acc = 0;
    int beg = g_off[n], end = g_off[n + 1];
    const __half2* X = (const __half2*)g_xl2h;    // row = 64 half2
    int j = beg;
    for (; j + 3 < end; j += 4) {
        int s0 = g_srcs[j], s1 = g_srcs[j + 1], s2 = g_srcs[j + 2], s3 = g_srcs[j + 3];
        float e0 = g_as2[s0], e1 = g_as2[s1], e2 = g_as2[s2], e3 = g_as2[s3];
        __half2 x0 = X[s0 * 64 + col];
        __half2 x1 = X[s1 * 64 + col];
        __half2 x2 = X[s2 * 64 + col];
        __half2 x3 = X[s3 * 64 + col];
        float p0 = __expf(lrelu(e0 + adv));
        float p1 = __expf(lrelu(e1 + adv));
        float p2 = __expf(lrelu(e2 + adv));
        float p3 = __expf(lrelu(e3 + adv));
        s += (p0 + p1) + (p2 + p3);
        float2 f0 = __half22float2(x0), f1 = __half22float2(x1);
        float2 f2 = __half22float2(x2), f3 = __half22float2(x3);
        acc = ffma2(pk2(p0, p0), pk2(f0.x, f0.y), acc);
        acc = ffma2(pk2(p1, p1), pk2(f1.x, f1.y), acc);
        acc = ffma2(pk2(p2, p2), pk2(f2.x, f2.y), acc);
        acc = ffma2(pk2(p3, p3), pk2(f3.x, f3.y), acc);
    }
    for (; j < end; j++) {
        int s0 = g_srcs[j];
        float e0 = g_as2[s0];
        __half2 x0 = X[s0 * 64 + col];
        float p0 = __expf(lrelu(e0 + adv));
        s += p0;
        float2 f0 = __half22float2(x0);
        acc = ffma2(pk2(p0, p0), pk2(f0.x, f0.y), acc);
    }
    float inv = 1.f / s;
    float2 u = upk2(acc);
    float2 bb = ((const float2*)b2)[col];
    float v0 = u.x * inv + bb.x; v0 = v0 > 0.f ? v0 : (__expf(v0) - 1.f);
    float v1 = u.y * inv + bb.y; v1 = v1 > 0.f ? v1 : (__expf(v1) - 1.f);
    int b = idx_at(batch, n);
    float* pp = &g_pool[b * 128 + col * 2];
    atomicAdd(pp + 0, v0);
    atomicAdd(pp + 1, v1);
    if (col == 0) atomicAdd(&g_cnt[b], 1);
}

// ---------------- final: mean pool -> out ----------------
__global__ void k_final(float* __restrict__ out) {
    int i = blockIdx.x * 256 + threadIdx.x;
    if (i < NG * 128) {
        int g = i >> 7;
        out[i] = g_pool[i] / fmaxf((float)g_cnt[g], 1.f);
    }
}

extern "C" void kernel_launch(void* const* d_in, const int* in_sizes, int n_in,
                              void* d_out, int out_size) {
    const float* x   = (const float*)d_in[0];
    const void*  ei  = d_in[1];
    const void*  bat = d_in[2];
    const float* W1  = (const float*)d_in[3];
    const float* as1 = (const float*)d_in[4];
    const float* ad1 = (const float*)d_in[5];
    const float* b1  = (const float*)d_in[6];
    const float* W2  = (const float*)d_in[7];
    const float* as2 = (const float*)d_in[8];
    const float* ad2 = (const float*)d_in[9];
    const float* b2  = (const float*)d_in[10];
    float* out = (float*)d_out;

    k_zero<<<NSB, 256>>>((const int*)ei);
    k_hist<<<(NE / 2 + 255) / 256, 256>>>(ei);
    k_scan1<<<NSB, 256>>>();
    k_scan2<<<1, 256>>>();
    k_scan3<<<NSB, 256>>>();
    k_fill<<<(NE / 2 + 255) / 256, 256>>>(ei);
    k_gemm1<<<NN / 16, 128>>>(x, W1, as1, ad1);
    k_agg1<<<NN / 8, 256>>>(b1);
    k_gemm2<<<NN / 8, 128>>>(W2, as2, ad2);
    k_agg2<<<NN / 4, 256>>>(b2, bat);
    k_final<<<32, 256>>>(out);
}